// round 3
// baseline (speedup 1.0000x reference)
#include <cuda_runtime.h>
#include <cuda_bf16.h>
#include <math.h>

#define NN 50000
#define EE 200000
#define E2 (EE + NN)
#define HD 128

// ---------------- scratch (static device globals; no allocation) ----------------
__device__ int   g_down[NN];
__device__ float g_h[NN * HD];
__device__ float g_h2[NN * HD];
__device__ float g_xh[(size_t)NN * 512];
__device__ float g_als[NN * 4];
__device__ float g_ald[NN * 4];
__device__ int   g_cnt[NN];
__device__ int   g_rowtmp[NN];
__device__ int   g_bsum[64];
__device__ int   g_rowptr[NN + 1];
__device__ int   g_cursor[NN];
__device__ int   g_csrsrc[E2];
__device__ float g_p[NN * HD];
__device__ float g_q[NN * HD];

// ---------------- small helpers ----------------
__global__ void k_zero_misc() {
    int i = blockIdx.x * blockDim.x + threadIdx.x;
    if (i < NN) { g_down[i] = 0; g_cnt[i] = 0; }
}

__global__ void k_down(const int* __restrict__ src, const int* __restrict__ dst,
                       const int* __restrict__ shock) {
    int e = blockIdx.x * blockDim.x + threadIdx.x;
    if (e >= EE) return;
    if (shock[src[e]] != 0) g_down[dst[e]] = 1;
}

__global__ void k_count(const int* __restrict__ dst) {
    int e = blockIdx.x * blockDim.x + threadIdx.x;
    if (e >= E2) return;
    int d = (e < EE) ? dst[e] : (e - EE);
    atomicAdd(&g_cnt[d], 1);
}

__global__ void k_scan1() {
    __shared__ int sh[1024];
    int tid = threadIdx.x;
    int i = blockIdx.x * 1024 + tid;
    int v = (i < NN) ? g_cnt[i] : 0;
    sh[tid] = v;
    __syncthreads();
    for (int off = 1; off < 1024; off <<= 1) {
        int t = (tid >= off) ? sh[tid - off] : 0;
        __syncthreads();
        sh[tid] += t;
        __syncthreads();
    }
    int incl = sh[tid];
    if (i < NN) g_rowtmp[i] = incl - v;
    if (tid == 1023) g_bsum[blockIdx.x] = incl;
}

__global__ void k_scan2(int nb) {
    if (threadIdx.x == 0 && blockIdx.x == 0) {
        int acc = 0;
        for (int b = 0; b < nb; b++) { int t = g_bsum[b]; g_bsum[b] = acc; acc += t; }
    }
}

__global__ void k_scan3() {
    int i = blockIdx.x * blockDim.x + threadIdx.x;
    if (i >= NN) return;
    int r = g_rowtmp[i] + g_bsum[i >> 10];
    g_rowptr[i] = r;
    g_cursor[i] = r;
    if (i == NN - 1) g_rowptr[NN] = E2;
}

__global__ void k_scatter(const int* __restrict__ src, const int* __restrict__ dst) {
    int e = blockIdx.x * blockDim.x + threadIdx.x;
    if (e >= E2) return;
    int s, d;
    if (e < EE) { s = src[e]; d = dst[e]; } else { s = e - EE; d = e - EE; }
    int pos = atomicAdd(&g_cursor[d], 1);
    g_csrsrc[pos] = s;
}

// ---------------- node encoder: xa@W + b -> LN -> relu ----------------
__global__ void k_encoder(const float* __restrict__ x, const int* __restrict__ shock,
                          const float* __restrict__ W, const float* __restrict__ b,
                          const float* __restrict__ lng, const float* __restrict__ lnb,
                          float* __restrict__ hout) {
    int n = blockIdx.x;
    int t = threadIdx.x;
    __shared__ float xa[18];
    __shared__ float r1[4], r2[4];
    if (t < 16)      xa[t]  = x[n * 16 + t];
    else if (t == 16) xa[16] = (float)shock[n];
    else if (t == 17) xa[17] = (float)g_down[n];
    __syncthreads();
    float v = b[t];
#pragma unroll
    for (int j = 0; j < 18; j++) v += xa[j] * W[j * HD + t];
    float s = v, s2 = v * v;
    for (int off = 16; off > 0; off >>= 1) {
        s  += __shfl_down_sync(0xffffffffu, s,  off);
        s2 += __shfl_down_sync(0xffffffffu, s2, off);
    }
    if ((t & 31) == 0) { r1[t >> 5] = s; r2[t >> 5] = s2; }
    __syncthreads();
    float mu  = (r1[0] + r1[1] + r1[2] + r1[3]) * (1.0f / HD);
    float var = (r2[0] + r2[1] + r2[2] + r2[3]) * (1.0f / HD) - mu * mu;
    float y = (v - mu) * rsqrtf(var + 1e-5f) * lng[t] + lnb[t];
    hout[n * HD + t] = fmaxf(y, 0.0f);
}

// ---------------- generic fp32 GEMM: C[M,N] = A[M,K] @ B[K,N] ----------------
__global__ __launch_bounds__(256) void gemm64(const float* __restrict__ A,
                                              const float* __restrict__ B,
                                              float* __restrict__ C,
                                              int M, int N, int K) {
    __shared__ __align__(16) float As[16][64];
    __shared__ __align__(16) float Bs[16][64];
    int row0 = blockIdx.x * 64;
    int col0 = blockIdx.y * 64;
    int tid = threadIdx.x;
    int tx = tid & 15, ty = tid >> 4;
    float acc[4][4];
#pragma unroll
    for (int i = 0; i < 4; i++)
#pragma unroll
        for (int j = 0; j < 4; j++) acc[i][j] = 0.0f;

    for (int k0 = 0; k0 < K; k0 += 16) {
        // A tile: 64 rows x 16 k, float4 per thread
        int m  = tid >> 2;
        int k4 = (tid & 3) * 4;
        float4 av = make_float4(0.f, 0.f, 0.f, 0.f);
        if (row0 + m < M)
            av = *(const float4*)&A[(size_t)(row0 + m) * K + k0 + k4];
        As[k4 + 0][m] = av.x; As[k4 + 1][m] = av.y;
        As[k4 + 2][m] = av.z; As[k4 + 3][m] = av.w;
        // B tile: 16 k x 64 cols
        int kk = tid >> 4;
        int n4 = (tid & 15) * 4;
        float4 bv = *(const float4*)&B[(size_t)(k0 + kk) * N + col0 + n4];
        *(float4*)&Bs[kk][n4] = bv;
        __syncthreads();
#pragma unroll
        for (int k = 0; k < 16; k++) {
            float4 a = *(float4*)&As[k][ty * 4];
            float4 b = *(float4*)&Bs[k][tx * 4];
            acc[0][0] += a.x * b.x; acc[0][1] += a.x * b.y; acc[0][2] += a.x * b.z; acc[0][3] += a.x * b.w;
            acc[1][0] += a.y * b.x; acc[1][1] += a.y * b.y; acc[1][2] += a.y * b.z; acc[1][3] += a.y * b.w;
            acc[2][0] += a.z * b.x; acc[2][1] += a.z * b.y; acc[2][2] += a.z * b.z; acc[2][3] += a.z * b.w;
            acc[3][0] += a.w * b.x; acc[3][1] += a.w * b.y; acc[3][2] += a.w * b.z; acc[3][3] += a.w * b.w;
        }
        __syncthreads();
    }
#pragma unroll
    for (int i = 0; i < 4; i++) {
        int r = row0 + ty * 4 + i;
        if (r < M) {
            float4 o = make_float4(acc[i][0], acc[i][1], acc[i][2], acc[i][3]);
            *(float4*)&C[(size_t)r * N + col0 + tx * 4] = o;
        }
    }
}

// ---------------- per-node attention logits ----------------
__global__ void k_logits(const float* __restrict__ xh,
                         const float* __restrict__ att_src,
                         const float* __restrict__ att_dst) {
    int n = blockIdx.x;
    int t = threadIdx.x;
    int head = t >> 5, lane = t & 31;
    const float4* xv = (const float4*)(xh + (size_t)n * 512 + head * 128);
    float4 v = xv[lane];
    float4 a = ((const float4*)(att_src + head * 128))[lane];
    float4 ad = ((const float4*)(att_dst + head * 128))[lane];
    float ds = v.x * a.x + v.y * a.y + v.z * a.z + v.w * a.w;
    float dd = v.x * ad.x + v.y * ad.y + v.z * ad.z + v.w * ad.w;
    for (int off = 16; off > 0; off >>= 1) {
        ds += __shfl_down_sync(0xffffffffu, ds, off);
        dd += __shfl_down_sync(0xffffffffu, dd, off);
    }
    if (lane == 0) { g_als[n * 4 + head] = ds; g_ald[n * 4 + head] = dd; }
}

// ------- fused GAT gather: softmax + weighted sum + head-mean + bias + BN (+relu) -------
__global__ void k_gather(const float* __restrict__ xh,
                         const float* __restrict__ bias,
                         const float* __restrict__ bng, const float* __restrict__ bnb,
                         const float* __restrict__ bnm, const float* __restrict__ bnv,
                         int do_relu, float* __restrict__ hout) {
    int node = blockIdx.x * 4 + (threadIdx.x >> 5);
    int lane = threadIdx.x & 31;
    if (node >= NN) return;
    int beg = g_rowptr[node], end = g_rowptr[node + 1];
    int h = lane & 3;
    float myald = g_ald[node * 4 + h];

    // pass 1: per-head max of leaky_relu(al_src[s]+al_dst[n])
    float mx = -1e30f;
    for (int i = beg; i < end; i++) {
        int s = g_csrsrc[i];
        float a = g_als[s * 4 + h] + myald;
        a = (a >= 0.0f) ? a : 0.2f * a;
        mx = fmaxf(mx, a);
    }

    // pass 2: exp, sum, weighted accumulate of xh[s]
    float4 acc0 = make_float4(0, 0, 0, 0), acc1 = acc0, acc2 = acc0, acc3 = acc0;
    float sum = 0.0f;
    for (int i = beg; i < end; i++) {
        int s = g_csrsrc[i];
        float a = g_als[s * 4 + h] + myald;
        a = (a >= 0.0f) ? a : 0.2f * a;
        float w = expf(a - mx);
        sum += w;
        float w0 = __shfl_sync(0xffffffffu, w, 0);
        float w1 = __shfl_sync(0xffffffffu, w, 1);
        float w2 = __shfl_sync(0xffffffffu, w, 2);
        float w3 = __shfl_sync(0xffffffffu, w, 3);
        const float4* xp = (const float4*)(xh + (size_t)s * 512);
        float4 v0 = xp[lane];
        float4 v1 = xp[32 + lane];
        float4 v2 = xp[64 + lane];
        float4 v3 = xp[96 + lane];
        acc0.x += w0 * v0.x; acc0.y += w0 * v0.y; acc0.z += w0 * v0.z; acc0.w += w0 * v0.w;
        acc1.x += w1 * v1.x; acc1.y += w1 * v1.y; acc1.z += w1 * v1.z; acc1.w += w1 * v1.w;
        acc2.x += w2 * v2.x; acc2.y += w2 * v2.y; acc2.z += w2 * v2.z; acc2.w += w2 * v2.w;
        acc3.x += w3 * v3.x; acc3.y += w3 * v3.y; acc3.z += w3 * v3.z; acc3.w += w3 * v3.w;
    }
    float s0 = __shfl_sync(0xffffffffu, sum, 0);
    float s1 = __shfl_sync(0xffffffffu, sum, 1);
    float s2 = __shfl_sync(0xffffffffu, sum, 2);
    float s3 = __shfl_sync(0xffffffffu, sum, 3);
    float i0 = 1.0f / (s0 + 1e-16f), i1 = 1.0f / (s1 + 1e-16f);
    float i2 = 1.0f / (s2 + 1e-16f), i3 = 1.0f / (s3 + 1e-16f);

    int c = lane * 4;
    float4 bia = *(const float4*)&bias[c];
    float4 g4  = *(const float4*)&bng[c];
    float4 b4  = *(const float4*)&bnb[c];
    float4 m4  = *(const float4*)&bnm[c];
    float4 v4  = *(const float4*)&bnv[c];
    float4 o;
    o.x = 0.25f * (acc0.x * i0 + acc1.x * i1 + acc2.x * i2 + acc3.x * i3) + bia.x;
    o.y = 0.25f * (acc0.y * i0 + acc1.y * i1 + acc2.y * i2 + acc3.y * i3) + bia.y;
    o.z = 0.25f * (acc0.z * i0 + acc1.z * i1 + acc2.z * i2 + acc3.z * i3) + bia.z;
    o.w = 0.25f * (acc0.w * i0 + acc1.w * i1 + acc2.w * i2 + acc3.w * i3) + bia.w;
    o.x = (o.x - m4.x) * rsqrtf(v4.x + 1e-5f) * g4.x + b4.x;
    o.y = (o.y - m4.y) * rsqrtf(v4.y + 1e-5f) * g4.y + b4.y;
    o.z = (o.z - m4.z) * rsqrtf(v4.z + 1e-5f) * g4.z + b4.z;
    o.w = (o.w - m4.w) * rsqrtf(v4.w + 1e-5f) * g4.w + b4.w;
    if (do_relu) {
        o.x = fmaxf(o.x, 0.f); o.y = fmaxf(o.y, 0.f);
        o.z = fmaxf(o.z, 0.f); o.w = fmaxf(o.w, 0.f);
    }
    *(float4*)&hout[(size_t)node * HD + c] = o;
}

// ------- fused edge MLP: z1 = relu(LN(p[s]+q[d]+eattr@Wc+b1)); z2=relu(z1@W2+b2); out=z2@W3+b3 -------
__global__ void k_edge_mlp(const int* __restrict__ src, const int* __restrict__ dst,
                           const float* __restrict__ eattr,
                           const float* __restrict__ em1b, const float* __restrict__ wc,
                           const float* __restrict__ lng, const float* __restrict__ lnb,
                           const float* __restrict__ w2, const float* __restrict__ b2,
                           const float* __restrict__ w3, const float* __restrict__ b3,
                           float* __restrict__ out) {
    int e = blockIdx.x;
    int t = threadIdx.x;
    __shared__ float sa[8];
    __shared__ float sz1[128];
    __shared__ float sp[128];
    __shared__ float r1[4], r2[4];
    int s = src[e], d = dst[e];
    if (t < 8) sa[t] = eattr[e * 8 + t];
    __syncthreads();
    float v = g_p[s * HD + t] + g_q[d * HD + t] + em1b[t];
#pragma unroll
    for (int j = 0; j < 8; j++) v += sa[j] * wc[j * HD + t];
    // LayerNorm over 128
    float su = v, sq = v * v;
    for (int off = 16; off > 0; off >>= 1) {
        su += __shfl_down_sync(0xffffffffu, su, off);
        sq += __shfl_down_sync(0xffffffffu, sq, off);
    }
    if ((t & 31) == 0) { r1[t >> 5] = su; r2[t >> 5] = sq; }
    __syncthreads();
    float mu  = (r1[0] + r1[1] + r1[2] + r1[3]) * (1.0f / HD);
    float var = (r2[0] + r2[1] + r2[2] + r2[3]) * (1.0f / HD) - mu * mu;
    float y = (v - mu) * rsqrtf(var + 1e-5f) * lng[t] + lnb[t];
    sz1[t] = fmaxf(y, 0.0f);
    __syncthreads();
    // z2 = relu(z1 @ W2 + b2) : [128] @ [128,64]
    int o = t & 63, half = t >> 6;
    float acc = 0.0f;
    const float* w2p = w2 + half * 64 * 64 + o;
    const float* zp  = sz1 + half * 64;
#pragma unroll 8
    for (int k = 0; k < 64; k++) acc += zp[k] * w2p[k * 64];
    sp[t] = acc;
    __syncthreads();
    float z2 = 0.0f;
    if (t < 64) {
        z2 = fmaxf(sp[t] + sp[t + 64] + b2[t], 0.0f);
        z2 *= w3[t];
    }
    for (int off = 16; off > 0; off >>= 1) z2 += __shfl_down_sync(0xffffffffu, z2, off);
    __syncthreads();
    if (t == 0)  r1[0] = z2;
    if (t == 32) r1[1] = z2;
    __syncthreads();
    if (t == 0) out[e] = r1[0] + r1[1] + b3[0];
}

// ---------------- launch ----------------
extern "C" void kernel_launch(void* const* d_in, const int* in_sizes, int n_in,
                              void* d_out, int out_size) {
    const float* x       = (const float*)d_in[0];
    const int*   ei      = (const int*)d_in[1];
    const float* eattr   = (const float*)d_in[2];
    const int*   shock   = (const int*)d_in[3];
    const float* enc_w   = (const float*)d_in[4];
    const float* enc_b   = (const float*)d_in[5];
    const float* enc_lng = (const float*)d_in[6];
    const float* enc_lnb = (const float*)d_in[7];
    const float* gat_w   = (const float*)d_in[8];
    const float* att_src = (const float*)d_in[9];
    const float* att_dst = (const float*)d_in[10];
    const float* gat_bias= (const float*)d_in[11];
    const float* bn_g    = (const float*)d_in[12];
    const float* bn_b    = (const float*)d_in[13];
    const float* bn_m    = (const float*)d_in[14];
    const float* bn_v    = (const float*)d_in[15];
    const float* em1_w   = (const float*)d_in[16];
    const float* em1_b   = (const float*)d_in[17];
    const float* em_lng  = (const float*)d_in[18];
    const float* em_lnb  = (const float*)d_in[19];
    const float* em2_w   = (const float*)d_in[20];
    const float* em2_b   = (const float*)d_in[21];
    const float* em3_w   = (const float*)d_in[22];
    const float* em3_b   = (const float*)d_in[23];
    const int* src = ei;
    const int* dst = ei + EE;
    float* out = (float*)d_out;

    float *ph, *ph2, *pxh, *pp, *pq;
    cudaGetSymbolAddress((void**)&ph,  g_h);
    cudaGetSymbolAddress((void**)&ph2, g_h2);
    cudaGetSymbolAddress((void**)&pxh, g_xh);
    cudaGetSymbolAddress((void**)&pp,  g_p);
    cudaGetSymbolAddress((void**)&pq,  g_q);

    // graph prep: downstream flags + CSR by destination (with self-loops)
    k_zero_misc<<<(NN + 255) / 256, 256>>>();
    k_down<<<(EE + 255) / 256, 256>>>(src, dst, shock);
    k_count<<<(E2 + 255) / 256, 256>>>(dst);
    int nb = (NN + 1023) / 1024;
    k_scan1<<<nb, 1024>>>();
    k_scan2<<<1, 32>>>(nb);
    k_scan3<<<(NN + 255) / 256, 256>>>();
    k_scatter<<<(E2 + 255) / 256, 256>>>(src, dst);

    // node encoder
    k_encoder<<<NN, 128>>>(x, shock, enc_w, enc_b, enc_lng, enc_lnb, ph);

    // 3 GAT layers
    float* hin = ph;
    float* hout = ph2;
    for (int l = 0; l < 3; l++) {
        gemm64<<<dim3((NN + 63) / 64, 512 / 64), 256>>>(hin, gat_w + (size_t)l * HD * 512, pxh, NN, 512, HD);
        k_logits<<<NN, 128>>>(pxh, att_src + l * 4 * HD, att_dst + l * 4 * HD);
        k_gather<<<(NN + 3) / 4, 128>>>(pxh, gat_bias + l * HD,
                                        bn_g + l * HD, bn_b + l * HD, bn_m + l * HD, bn_v + l * HD,
                                        (l < 2) ? 1 : 0, hout);
        float* tmp = hin; hin = hout; hout = tmp;
    }
    // hin now holds the final node embeddings

    // edge MLP first layer factored: p = h @ W_a (rows 0..127), q = h @ W_b (rows 128..255)
    gemm64<<<dim3((NN + 63) / 64, 2), 256>>>(hin, em1_w,            pp, NN, HD, HD);
    gemm64<<<dim3((NN + 63) / 64, 2), 256>>>(hin, em1_w + 128 * HD, pq, NN, HD, HD);

    // fused edge predictor
    k_edge_mlp<<<EE, 128>>>(src, dst, eattr, em1_b, em1_w + 256 * HD,
                            em_lng, em_lnb, em2_w, em2_b, em3_w, em3_b, out);
}

// round 4
// speedup vs baseline: 1.3561x; 1.3561x over previous
#include <cuda_runtime.h>
#include <cuda_bf16.h>
#include <math.h>

#define NN 50000
#define EE 200000
#define E2 (EE + NN)
#define HD 128

// ---------------- scratch (static device globals; no allocation) ----------------
__device__ int   g_down[NN];
__device__ float g_h[NN * HD];
__device__ float g_h2[NN * HD];
__device__ float g_xh[(size_t)NN * 512];
__device__ float g_als[NN * 4];
__device__ float g_ald[NN * 4];
__device__ int   g_cnt[NN];
__device__ int   g_rowtmp[NN];
__device__ int   g_bsum[64];
__device__ int   g_rowptr[NN + 1];
__device__ int   g_cursor[NN];
__device__ int   g_csrsrc[E2];
__device__ float g_p[NN * HD];
__device__ float g_q[NN * HD];

// ---------------- small helpers ----------------
__global__ void k_zero_misc() {
    int i = blockIdx.x * blockDim.x + threadIdx.x;
    if (i < NN) { g_down[i] = 0; g_cnt[i] = 0; }
}

__global__ void k_down(const int* __restrict__ src, const int* __restrict__ dst,
                       const int* __restrict__ shock) {
    int e = blockIdx.x * blockDim.x + threadIdx.x;
    if (e >= EE) return;
    if (shock[src[e]] != 0) g_down[dst[e]] = 1;
}

__global__ void k_count(const int* __restrict__ dst) {
    int e = blockIdx.x * blockDim.x + threadIdx.x;
    if (e >= E2) return;
    int d = (e < EE) ? dst[e] : (e - EE);
    atomicAdd(&g_cnt[d], 1);
}

__global__ void k_scan1() {
    __shared__ int sh[1024];
    int tid = threadIdx.x;
    int i = blockIdx.x * 1024 + tid;
    int v = (i < NN) ? g_cnt[i] : 0;
    sh[tid] = v;
    __syncthreads();
    for (int off = 1; off < 1024; off <<= 1) {
        int t = (tid >= off) ? sh[tid - off] : 0;
        __syncthreads();
        sh[tid] += t;
        __syncthreads();
    }
    int incl = sh[tid];
    if (i < NN) g_rowtmp[i] = incl - v;
    if (tid == 1023) g_bsum[blockIdx.x] = incl;
}

__global__ void k_scan2(int nb) {
    if (threadIdx.x == 0 && blockIdx.x == 0) {
        int acc = 0;
        for (int b = 0; b < nb; b++) { int t = g_bsum[b]; g_bsum[b] = acc; acc += t; }
    }
}

__global__ void k_scan3() {
    int i = blockIdx.x * blockDim.x + threadIdx.x;
    if (i >= NN) return;
    int r = g_rowtmp[i] + g_bsum[i >> 10];
    g_rowptr[i] = r;
    g_cursor[i] = r;
    if (i == NN - 1) g_rowptr[NN] = E2;
}

__global__ void k_scatter(const int* __restrict__ src, const int* __restrict__ dst) {
    int e = blockIdx.x * blockDim.x + threadIdx.x;
    if (e >= E2) return;
    int s, d;
    if (e < EE) { s = src[e]; d = dst[e]; } else { s = e - EE; d = e - EE; }
    int pos = atomicAdd(&g_cursor[d], 1);
    g_csrsrc[pos] = s;
}

// ---------------- node encoder: xa@W + b -> LN -> relu ----------------
__global__ void k_encoder(const float* __restrict__ x, const int* __restrict__ shock,
                          const float* __restrict__ W, const float* __restrict__ b,
                          const float* __restrict__ lng, const float* __restrict__ lnb,
                          float* __restrict__ hout) {
    int n = blockIdx.x;
    int t = threadIdx.x;
    __shared__ float xa[18];
    __shared__ float r1[4], r2[4];
    if (t < 16)      xa[t]  = x[n * 16 + t];
    else if (t == 16) xa[16] = (float)shock[n];
    else if (t == 17) xa[17] = (float)g_down[n];
    __syncthreads();
    float v = b[t];
#pragma unroll
    for (int j = 0; j < 18; j++) v += xa[j] * W[j * HD + t];
    float s = v, s2 = v * v;
    for (int off = 16; off > 0; off >>= 1) {
        s  += __shfl_down_sync(0xffffffffu, s,  off);
        s2 += __shfl_down_sync(0xffffffffu, s2, off);
    }
    if ((t & 31) == 0) { r1[t >> 5] = s; r2[t >> 5] = s2; }
    __syncthreads();
    float mu  = (r1[0] + r1[1] + r1[2] + r1[3]) * (1.0f / HD);
    float var = (r2[0] + r2[1] + r2[2] + r2[3]) * (1.0f / HD) - mu * mu;
    float y = (v - mu) * rsqrtf(var + 1e-5f) * lng[t] + lnb[t];
    hout[n * HD + t] = fmaxf(y, 0.0f);
}

// ---------------- fp32 GEMM: C[M,N] = A[M,K] @ B[K,N], 128x128 tile, 8x8/thread ----
// Optionally fuses per-head attention logits: when att_s != nullptr, each
// column-block (blockIdx.y) is one head's 128 channels; computes
// als[row,head] = dot(C_row_head, att_s[head]) and ald likewise, via in-register
// reduction over the accumulators (width-16 shuffle).
__global__ __launch_bounds__(256) void gemm128(const float* __restrict__ A,
                                               const float* __restrict__ B,
                                               float* __restrict__ C,
                                               int M, int N, int K,
                                               const float* __restrict__ att_s,
                                               const float* __restrict__ att_d) {
    __shared__ __align__(16) float As[16][136];
    __shared__ __align__(16) float Bs[16][128];
    int tid = threadIdx.x;
    int m0 = blockIdx.x * 128, n0 = blockIdx.y * 128;
    int tx = tid & 15, ty = tid >> 4;
    float acc[8][8];
#pragma unroll
    for (int i = 0; i < 8; i++)
#pragma unroll
        for (int j = 0; j < 8; j++) acc[i][j] = 0.0f;

    int arow = tid >> 1;
    int ak   = (tid & 1) * 4;
    int brow = tid >> 5;           // 0..7
    int bcol = (tid & 31) * 4;
    bool avalid = (m0 + arow) < M;
    const float* Aptr = A + (size_t)(m0 + arow) * K + ak;

    for (int k0 = 0; k0 < K; k0 += 16) {
        float4 av0 = make_float4(0, 0, 0, 0), av1 = av0;
        if (avalid) {
            av0 = *(const float4*)(Aptr + k0);
            av1 = *(const float4*)(Aptr + k0 + 8);
        }
        float4 bv0 = *(const float4*)&B[(size_t)(k0 + brow) * N + n0 + bcol];
        float4 bv1 = *(const float4*)&B[(size_t)(k0 + brow + 8) * N + n0 + bcol];
        __syncthreads();
        As[ak + 0][arow] = av0.x; As[ak + 1][arow] = av0.y;
        As[ak + 2][arow] = av0.z; As[ak + 3][arow] = av0.w;
        As[ak + 8][arow] = av1.x; As[ak + 9][arow] = av1.y;
        As[ak + 10][arow] = av1.z; As[ak + 11][arow] = av1.w;
        *(float4*)&Bs[brow][bcol]     = bv0;
        *(float4*)&Bs[brow + 8][bcol] = bv1;
        __syncthreads();
#pragma unroll
        for (int k = 0; k < 16; k++) {
            float4 a0 = *(float4*)&As[k][ty * 8];
            float4 a1 = *(float4*)&As[k][ty * 8 + 4];
            float4 b0 = *(float4*)&Bs[k][tx * 4];
            float4 b1 = *(float4*)&Bs[k][tx * 4 + 64];
            float am[8] = {a0.x, a0.y, a0.z, a0.w, a1.x, a1.y, a1.z, a1.w};
            float bn[8] = {b0.x, b0.y, b0.z, b0.w, b1.x, b1.y, b1.z, b1.w};
#pragma unroll
            for (int i = 0; i < 8; i++)
#pragma unroll
                for (int j = 0; j < 8; j++) acc[i][j] += am[i] * bn[j];
        }
    }

#pragma unroll
    for (int i = 0; i < 8; i++) {
        int r = m0 + ty * 8 + i;
        if (r < M) {
            float4 o0 = make_float4(acc[i][0], acc[i][1], acc[i][2], acc[i][3]);
            float4 o1 = make_float4(acc[i][4], acc[i][5], acc[i][6], acc[i][7]);
            *(float4*)&C[(size_t)r * N + n0 + tx * 4]      = o0;
            *(float4*)&C[(size_t)r * N + n0 + 64 + tx * 4] = o1;
        }
    }

    if (att_s) {
        int head = blockIdx.y;
        float4 as0 = ((const float4*)(att_s + head * 128))[tx];
        float4 as1 = ((const float4*)(att_s + head * 128 + 64))[tx];
        float4 ad0 = ((const float4*)(att_d + head * 128))[tx];
        float4 ad1 = ((const float4*)(att_d + head * 128 + 64))[tx];
#pragma unroll
        for (int i = 0; i < 8; i++) {
            float ps = acc[i][0] * as0.x + acc[i][1] * as0.y + acc[i][2] * as0.z + acc[i][3] * as0.w
                     + acc[i][4] * as1.x + acc[i][5] * as1.y + acc[i][6] * as1.z + acc[i][7] * as1.w;
            float pd = acc[i][0] * ad0.x + acc[i][1] * ad0.y + acc[i][2] * ad0.z + acc[i][3] * ad0.w
                     + acc[i][4] * ad1.x + acc[i][5] * ad1.y + acc[i][6] * ad1.z + acc[i][7] * ad1.w;
#pragma unroll
            for (int off = 8; off > 0; off >>= 1) {
                ps += __shfl_down_sync(0xffffffffu, ps, off, 16);
                pd += __shfl_down_sync(0xffffffffu, pd, off, 16);
            }
            int r = m0 + ty * 8 + i;
            if (tx == 0 && r < M) {
                g_als[r * 4 + head] = ps;
                g_ald[r * 4 + head] = pd;
            }
        }
    }
}

// ------- fused GAT gather: softmax + weighted sum + head-mean + bias + BN (+relu) -------
__global__ void k_gather(const float* __restrict__ xh,
                         const float* __restrict__ bias,
                         const float* __restrict__ bng, const float* __restrict__ bnb,
                         const float* __restrict__ bnm, const float* __restrict__ bnv,
                         int do_relu, float* __restrict__ hout) {
    int node = blockIdx.x * 4 + (threadIdx.x >> 5);
    int lane = threadIdx.x & 31;
    if (node >= NN) return;
    int beg = g_rowptr[node], end = g_rowptr[node + 1];
    int h = lane & 3;
    float myald = g_ald[node * 4 + h];

    float mx = -1e30f;
    for (int i = beg; i < end; i++) {
        int s = g_csrsrc[i];
        float a = g_als[s * 4 + h] + myald;
        a = (a >= 0.0f) ? a : 0.2f * a;
        mx = fmaxf(mx, a);
    }

    float4 acc0 = make_float4(0, 0, 0, 0), acc1 = acc0, acc2 = acc0, acc3 = acc0;
    float sum = 0.0f;
    for (int i = beg; i < end; i++) {
        int s = g_csrsrc[i];
        float a = g_als[s * 4 + h] + myald;
        a = (a >= 0.0f) ? a : 0.2f * a;
        float w = expf(a - mx);
        sum += w;
        float w0 = __shfl_sync(0xffffffffu, w, 0);
        float w1 = __shfl_sync(0xffffffffu, w, 1);
        float w2 = __shfl_sync(0xffffffffu, w, 2);
        float w3 = __shfl_sync(0xffffffffu, w, 3);
        const float4* xp = (const float4*)(xh + (size_t)s * 512);
        float4 v0 = xp[lane];
        float4 v1 = xp[32 + lane];
        float4 v2 = xp[64 + lane];
        float4 v3 = xp[96 + lane];
        acc0.x += w0 * v0.x; acc0.y += w0 * v0.y; acc0.z += w0 * v0.z; acc0.w += w0 * v0.w;
        acc1.x += w1 * v1.x; acc1.y += w1 * v1.y; acc1.z += w1 * v1.z; acc1.w += w1 * v1.w;
        acc2.x += w2 * v2.x; acc2.y += w2 * v2.y; acc2.z += w2 * v2.z; acc2.w += w2 * v2.w;
        acc3.x += w3 * v3.x; acc3.y += w3 * v3.y; acc3.z += w3 * v3.z; acc3.w += w3 * v3.w;
    }
    float s0 = __shfl_sync(0xffffffffu, sum, 0);
    float s1 = __shfl_sync(0xffffffffu, sum, 1);
    float s2 = __shfl_sync(0xffffffffu, sum, 2);
    float s3 = __shfl_sync(0xffffffffu, sum, 3);
    float i0 = 1.0f / (s0 + 1e-16f), i1 = 1.0f / (s1 + 1e-16f);
    float i2 = 1.0f / (s2 + 1e-16f), i3 = 1.0f / (s3 + 1e-16f);

    int c = lane * 4;
    float4 bia = *(const float4*)&bias[c];
    float4 g4  = *(const float4*)&bng[c];
    float4 b4  = *(const float4*)&bnb[c];
    float4 m4  = *(const float4*)&bnm[c];
    float4 v4  = *(const float4*)&bnv[c];
    float4 o;
    o.x = 0.25f * (acc0.x * i0 + acc1.x * i1 + acc2.x * i2 + acc3.x * i3) + bia.x;
    o.y = 0.25f * (acc0.y * i0 + acc1.y * i1 + acc2.y * i2 + acc3.y * i3) + bia.y;
    o.z = 0.25f * (acc0.z * i0 + acc1.z * i1 + acc2.z * i2 + acc3.z * i3) + bia.z;
    o.w = 0.25f * (acc0.w * i0 + acc1.w * i1 + acc2.w * i2 + acc3.w * i3) + bia.w;
    o.x = (o.x - m4.x) * rsqrtf(v4.x + 1e-5f) * g4.x + b4.x;
    o.y = (o.y - m4.y) * rsqrtf(v4.y + 1e-5f) * g4.y + b4.y;
    o.z = (o.z - m4.z) * rsqrtf(v4.z + 1e-5f) * g4.z + b4.z;
    o.w = (o.w - m4.w) * rsqrtf(v4.w + 1e-5f) * g4.w + b4.w;
    if (do_relu) {
        o.x = fmaxf(o.x, 0.f); o.y = fmaxf(o.y, 0.f);
        o.z = fmaxf(o.z, 0.f); o.w = fmaxf(o.w, 0.f);
    }
    *(float4*)&hout[(size_t)node * HD + c] = o;
}

// ------- fused edge MLP v2: 16 edges/block, register-tiled z1@W2 ---------------
// z1 = relu(LN(p[s]+q[d]+eattr@Wc+b1)); z2 = relu(z1@W2+b2); out = z2@W3+b3
__global__ __launch_bounds__(256) void k_edge_mlp2(
        const int* __restrict__ src, const int* __restrict__ dst,
        const float* __restrict__ eattr,
        const float* __restrict__ em1b, const float* __restrict__ wc,
        const float* __restrict__ lng, const float* __restrict__ lnb,
        const float* __restrict__ w2, const float* __restrict__ b2,
        const float* __restrict__ w3, const float* __restrict__ b3,
        float* __restrict__ out) {
    __shared__ float sz1[16][128];        // 8 KB
    __shared__ float spart[4][16][64];    // 16 KB
    __shared__ float sea[2][8];
    __shared__ float red1[2][4], red2[2][4];

    int tid = threadIdx.x;
    int e_base = blockIdx.x * 16;
    int t = tid & 127, half = tid >> 7;

    // Phase A: z1 for 16 edges, two at a time (one per 128-thread half)
    for (int g = 0; g < 8; g++) {
        int el = g * 2 + half;
        int e = e_base + el;
        int s = src[e], d = dst[e];
        if (t < 8) sea[half][t] = eattr[e * 8 + t];
        __syncthreads();
        float v = g_p[s * HD + t] + g_q[d * HD + t] + em1b[t];
#pragma unroll
        for (int j = 0; j < 8; j++) v += sea[half][j] * wc[j * HD + t];
        float su = v, sq = v * v;
#pragma unroll
        for (int off = 16; off > 0; off >>= 1) {
            su += __shfl_down_sync(0xffffffffu, su, off);
            sq += __shfl_down_sync(0xffffffffu, sq, off);
        }
        if ((t & 31) == 0) { red1[half][t >> 5] = su; red2[half][t >> 5] = sq; }
        __syncthreads();
        float mu  = (red1[half][0] + red1[half][1] + red1[half][2] + red1[half][3]) * (1.0f / HD);
        float var = (red2[half][0] + red2[half][1] + red2[half][2] + red2[half][3]) * (1.0f / HD) - mu * mu;
        float y = (v - mu) * rsqrtf(var + 1e-5f) * lng[t] + lnb[t];
        sz1[el][t] = fmaxf(y, 0.0f);
    }
    __syncthreads();

    // Phase B: spart[ks][e][o] = sum over k-slice of z1[e][k]*w2[k][o]
    // thread: 4 edges x 4 outputs, 32-k slice. w2 reads hit L1 (32 KB resident).
    {
        int o4 = (tid & 15) * 4;
        int eg = (tid >> 4) & 3;
        int ks = tid >> 6;
        float4 a0 = make_float4(0, 0, 0, 0), a1 = a0, a2 = a0, a3 = a0;
        int kbeg = ks * 32;
#pragma unroll 8
        for (int k = kbeg; k < kbeg + 32; k++) {
            float4 w4 = *(const float4*)&w2[k * 64 + o4];
            float z0 = sz1[eg * 4 + 0][k];
            float z1v = sz1[eg * 4 + 1][k];
            float z2v = sz1[eg * 4 + 2][k];
            float z3v = sz1[eg * 4 + 3][k];
            a0.x += z0 * w4.x;  a0.y += z0 * w4.y;  a0.z += z0 * w4.z;  a0.w += z0 * w4.w;
            a1.x += z1v * w4.x; a1.y += z1v * w4.y; a1.z += z1v * w4.z; a1.w += z1v * w4.w;
            a2.x += z2v * w4.x; a2.y += z2v * w4.y; a2.z += z2v * w4.z; a2.w += z2v * w4.w;
            a3.x += z3v * w4.x; a3.y += z3v * w4.y; a3.z += z3v * w4.z; a3.w += z3v * w4.w;
        }
        *(float4*)&spart[ks][eg * 4 + 0][o4] = a0;
        *(float4*)&spart[ks][eg * 4 + 1][o4] = a1;
        *(float4*)&spart[ks][eg * 4 + 2][o4] = a2;
        *(float4*)&spart[ks][eg * 4 + 3][o4] = a3;
    }
    __syncthreads();

    // Reduce k-slices, relu, dot with w3: 16 threads per edge
    {
        int e2 = tid >> 4;
        int ob = (tid & 15) * 4;
        float val = 0.0f;
#pragma unroll
        for (int i = 0; i < 4; i++) {
            int o = ob + i;
            float ssum = spart[0][e2][o] + spart[1][e2][o] + spart[2][e2][o] + spart[3][e2][o];
            float z2 = fmaxf(ssum + b2[o], 0.0f);
            val += z2 * w3[o];
        }
#pragma unroll
        for (int off = 8; off > 0; off >>= 1)
            val += __shfl_down_sync(0xffffffffu, val, off, 16);
        if ((tid & 15) == 0) out[e_base + e2] = val + b3[0];
    }
}

// ---------------- launch ----------------
extern "C" void kernel_launch(void* const* d_in, const int* in_sizes, int n_in,
                              void* d_out, int out_size) {
    const float* x       = (const float*)d_in[0];
    const int*   ei      = (const int*)d_in[1];
    const float* eattr   = (const float*)d_in[2];
    const int*   shock   = (const int*)d_in[3];
    const float* enc_w   = (const float*)d_in[4];
    const float* enc_b   = (const float*)d_in[5];
    const float* enc_lng = (const float*)d_in[6];
    const float* enc_lnb = (const float*)d_in[7];
    const float* gat_w   = (const float*)d_in[8];
    const float* att_src = (const float*)d_in[9];
    const float* att_dst = (const float*)d_in[10];
    const float* gat_bias= (const float*)d_in[11];
    const float* bn_g    = (const float*)d_in[12];
    const float* bn_b    = (const float*)d_in[13];
    const float* bn_m    = (const float*)d_in[14];
    const float* bn_v    = (const float*)d_in[15];
    const float* em1_w   = (const float*)d_in[16];
    const float* em1_b   = (const float*)d_in[17];
    const float* em_lng  = (const float*)d_in[18];
    const float* em_lnb  = (const float*)d_in[19];
    const float* em2_w   = (const float*)d_in[20];
    const float* em2_b   = (const float*)d_in[21];
    const float* em3_w   = (const float*)d_in[22];
    const float* em3_b   = (const float*)d_in[23];
    const int* src = ei;
    const int* dst = ei + EE;
    float* out = (float*)d_out;

    float *ph, *ph2, *pxh, *pp, *pq;
    cudaGetSymbolAddress((void**)&ph,  g_h);
    cudaGetSymbolAddress((void**)&ph2, g_h2);
    cudaGetSymbolAddress((void**)&pxh, g_xh);
    cudaGetSymbolAddress((void**)&pp,  g_p);
    cudaGetSymbolAddress((void**)&pq,  g_q);

    // graph prep: downstream flags + CSR by destination (with self-loops)
    k_zero_misc<<<(NN + 255) / 256, 256>>>();
    k_down<<<(EE + 255) / 256, 256>>>(src, dst, shock);
    k_count<<<(E2 + 255) / 256, 256>>>(dst);
    int nb = (NN + 1023) / 1024;
    k_scan1<<<nb, 1024>>>();
    k_scan2<<<1, 32>>>(nb);
    k_scan3<<<(NN + 255) / 256, 256>>>();
    k_scatter<<<(E2 + 255) / 256, 256>>>(src, dst);

    // node encoder
    k_encoder<<<NN, 128>>>(x, shock, enc_w, enc_b, enc_lng, enc_lnb, ph);

    // 3 GAT layers (logits fused into GEMM epilogue)
    float* hin = ph;
    float* hout = ph2;
    int gx = (NN + 127) / 128;
    for (int l = 0; l < 3; l++) {
        gemm128<<<dim3(gx, 4), 256>>>(hin, gat_w + (size_t)l * HD * 512, pxh, NN, 512, HD,
                                      att_src + l * 4 * HD, att_dst + l * 4 * HD);
        k_gather<<<(NN + 3) / 4, 128>>>(pxh, gat_bias + l * HD,
                                        bn_g + l * HD, bn_b + l * HD, bn_m + l * HD, bn_v + l * HD,
                                        (l < 2) ? 1 : 0, hout);
        float* tmp = hin; hin = hout; hout = tmp;
    }
    // hin now holds the final node embeddings

    // edge MLP first layer factored: p = h @ W_a (rows 0..127), q = h @ W_b (rows 128..255)
    gemm128<<<dim3(gx, 1), 256>>>(hin, em1_w,            pp, NN, HD, HD, nullptr, nullptr);
    gemm128<<<dim3(gx, 1), 256>>>(hin, em1_w + 128 * HD, pq, NN, HD, HD, nullptr, nullptr);

    // fused edge predictor (EE = 12500 * 16 exactly)
    k_edge_mlp2<<<EE / 16, 256>>>(src, dst, eattr, em1_b, em1_w + 256 * HD,
                                  em_lng, em_lnb, em2_w, em2_b, em3_w, em3_b, out);
}

// round 5
// speedup vs baseline: 1.8248x; 1.3456x over previous
#include <cuda_runtime.h>
#include <cuda_bf16.h>
#include <math.h>
#include <stdint.h>

#define NN 50000
#define EE 200000
#define E2 (EE + NN)
#define HD 128

// ---------------- scratch (static device globals; no allocation) ----------------
__device__ int   g_down[NN];
__device__ __align__(16) float g_h[NN * HD];
__device__ __align__(16) float g_h2[NN * HD];
__device__ __align__(16) float g_xh[(size_t)NN * 512];
__device__ float g_als[NN * 4];
__device__ float g_ald[NN * 4];
__device__ int   g_cnt[NN];
__device__ int   g_rowtmp[NN];
__device__ int   g_bsum[64];
__device__ int   g_rowptr[NN + 1];
__device__ int   g_cursor[NN];
__device__ int   g_csrsrc[E2];
__device__ __align__(16) float g_p[NN * HD];
__device__ __align__(16) float g_q[NN * HD];
__device__ __align__(16) float g_wsrc[3 * 4 * 128];
__device__ __align__(16) float g_wdst[3 * 4 * 128];

// ---------------- small helpers ----------------
__global__ void k_zero_misc() {
    int i = blockIdx.x * blockDim.x + threadIdx.x;
    if (i < NN) { g_down[i] = 0; g_cnt[i] = 0; }
}

__global__ void k_down(const int* __restrict__ src, const int* __restrict__ dst,
                       const int* __restrict__ shock) {
    int e = blockIdx.x * blockDim.x + threadIdx.x;
    if (e >= EE) return;
    if (shock[src[e]] != 0) g_down[dst[e]] = 1;
}

__global__ void k_count(const int* __restrict__ dst) {
    int e = blockIdx.x * blockDim.x + threadIdx.x;
    if (e >= E2) return;
    int d = (e < EE) ? dst[e] : (e - EE);
    atomicAdd(&g_cnt[d], 1);
}

__global__ void k_scan1() {
    __shared__ int sh[1024];
    int tid = threadIdx.x;
    int i = blockIdx.x * 1024 + tid;
    int v = (i < NN) ? g_cnt[i] : 0;
    sh[tid] = v;
    __syncthreads();
    for (int off = 1; off < 1024; off <<= 1) {
        int t = (tid >= off) ? sh[tid - off] : 0;
        __syncthreads();
        sh[tid] += t;
        __syncthreads();
    }
    int incl = sh[tid];
    if (i < NN) g_rowtmp[i] = incl - v;
    if (tid == 1023) g_bsum[blockIdx.x] = incl;
}

__global__ void k_scan2(int nb) {
    if (threadIdx.x == 0 && blockIdx.x == 0) {
        int acc = 0;
        for (int b = 0; b < nb; b++) { int t = g_bsum[b]; g_bsum[b] = acc; acc += t; }
    }
}

__global__ void k_scan3() {
    int i = blockIdx.x * blockDim.x + threadIdx.x;
    if (i >= NN) return;
    int r = g_rowtmp[i] + g_bsum[i >> 10];
    g_rowptr[i] = r;
    g_cursor[i] = r;
    if (i == NN - 1) g_rowptr[NN] = E2;
}

__global__ void k_scatter(const int* __restrict__ src, const int* __restrict__ dst) {
    int e = blockIdx.x * blockDim.x + threadIdx.x;
    if (e >= E2) return;
    int s, d;
    if (e < EE) { s = src[e]; d = dst[e]; } else { s = e - EE; d = e - EE; }
    int pos = atomicAdd(&g_cursor[d], 1);
    g_csrsrc[pos] = s;
}

// ---------------- node encoder: xa@W + b -> LN -> relu ----------------
__global__ void k_encoder(const float* __restrict__ x, const int* __restrict__ shock,
                          const float* __restrict__ W, const float* __restrict__ b,
                          const float* __restrict__ lng, const float* __restrict__ lnb,
                          float* __restrict__ hout) {
    int n = blockIdx.x;
    int t = threadIdx.x;
    __shared__ float xa[18];
    __shared__ float r1[4], r2[4];
    if (t < 16)      xa[t]  = x[n * 16 + t];
    else if (t == 16) xa[16] = (float)shock[n];
    else if (t == 17) xa[17] = (float)g_down[n];
    __syncthreads();
    float v = b[t];
#pragma unroll
    for (int j = 0; j < 18; j++) v += xa[j] * W[j * HD + t];
    float s = v, s2 = v * v;
    for (int off = 16; off > 0; off >>= 1) {
        s  += __shfl_down_sync(0xffffffffu, s,  off);
        s2 += __shfl_down_sync(0xffffffffu, s2, off);
    }
    if ((t & 31) == 0) { r1[t >> 5] = s; r2[t >> 5] = s2; }
    __syncthreads();
    float mu  = (r1[0] + r1[1] + r1[2] + r1[3]) * (1.0f / HD);
    float var = (r2[0] + r2[1] + r2[2] + r2[3]) * (1.0f / HD) - mu * mu;
    float y = (v - mu) * rsqrtf(var + 1e-5f) * lng[t] + lnb[t];
    hout[n * HD + t] = fmaxf(y, 0.0f);
}

// ---------------- tf32 tensor-core GEMM: C[M,N] = A[M,K] @ B[K,N] ----------------
// 128x128 tile, BK=32, 256 threads = 8 warps in 2(M) x 4(N), warp tile 64x32.
// Inputs rounded to tf32 (cvt.rna) at SMEM-store; fp32 accumulate.
__device__ __forceinline__ float to_tf32(float x) {
    float r;
    asm("cvt.rna.tf32.f32 %0, %1;" : "=f"(r) : "f"(x));
    return r;
}

__device__ __forceinline__ void mma_tf32(float* d, const uint32_t* a, const uint32_t* b) {
    asm volatile(
        "mma.sync.aligned.m16n8k8.row.col.f32.tf32.tf32.f32 "
        "{%0,%1,%2,%3}, {%4,%5,%6,%7}, {%8,%9}, {%0,%1,%2,%3};\n"
        : "+f"(d[0]), "+f"(d[1]), "+f"(d[2]), "+f"(d[3])
        : "r"(a[0]), "r"(a[1]), "r"(a[2]), "r"(a[3]), "r"(b[0]), "r"(b[1]));
}

__global__ __launch_bounds__(256) void gemm_tf32(const float* __restrict__ A,
                                                 const float* __restrict__ B,
                                                 float* __restrict__ C,
                                                 int M, int N, int K) {
    __shared__ __align__(16) float As[128][36];
    __shared__ __align__(16) float Bs[32][136];
    int tid = threadIdx.x;
    int m0 = blockIdx.x * 128, n0 = blockIdx.y * 128;
    int lane = tid & 31, wid = tid >> 5;
    int mbase = (wid & 1) * 64;
    int nbase = (wid >> 1) * 32;
    int r = lane >> 2, c = lane & 3;

    float acc[4][4][4];
#pragma unroll
    for (int i = 0; i < 4; i++)
#pragma unroll
        for (int j = 0; j < 4; j++)
#pragma unroll
            for (int q = 0; q < 4; q++) acc[i][j][q] = 0.0f;

    for (int kc = 0; kc < K; kc += 32) {
        __syncthreads();
        // A tile: 128 rows x 32 k  (8 float4 per row, 1024 float4)
#pragma unroll
        for (int i = 0; i < 4; i++) {
            int l4 = tid + i * 256;
            int row = l4 >> 3, c4 = (l4 & 7) << 2;
            float4 v = make_float4(0.f, 0.f, 0.f, 0.f);
            int gr = m0 + row;
            if (gr < M) v = *(const float4*)&A[(size_t)gr * K + kc + c4];
            v.x = to_tf32(v.x); v.y = to_tf32(v.y);
            v.z = to_tf32(v.z); v.w = to_tf32(v.w);
            *(float4*)&As[row][c4] = v;
        }
        // B tile: 32 k x 128 cols (32 float4 per row, 1024 float4)
#pragma unroll
        for (int i = 0; i < 4; i++) {
            int l4 = tid + i * 256;
            int row = l4 >> 5, c4 = (l4 & 31) << 2;
            float4 v = *(const float4*)&B[(size_t)(kc + row) * N + n0 + c4];
            v.x = to_tf32(v.x); v.y = to_tf32(v.y);
            v.z = to_tf32(v.z); v.w = to_tf32(v.w);
            *(float4*)&Bs[row][c4] = v;
        }
        __syncthreads();

#pragma unroll
        for (int k0 = 0; k0 < 32; k0 += 8) {
            uint32_t af[4][4], bf[4][2];
#pragma unroll
            for (int am = 0; am < 4; am++) {
                int row0 = mbase + am * 16 + r;
                af[am][0] = __float_as_uint(As[row0][k0 + c]);
                af[am][1] = __float_as_uint(As[row0 + 8][k0 + c]);
                af[am][2] = __float_as_uint(As[row0][k0 + c + 4]);
                af[am][3] = __float_as_uint(As[row0 + 8][k0 + c + 4]);
            }
#pragma unroll
            for (int an = 0; an < 4; an++) {
                int col0 = nbase + an * 8 + r;
                bf[an][0] = __float_as_uint(Bs[k0 + c][col0]);
                bf[an][1] = __float_as_uint(Bs[k0 + c + 4][col0]);
            }
#pragma unroll
            for (int am = 0; am < 4; am++)
#pragma unroll
                for (int an = 0; an < 4; an++)
                    mma_tf32(acc[am][an], af[am], bf[an]);
        }
    }

    // epilogue: fragment layout -> C
#pragma unroll
    for (int am = 0; am < 4; am++) {
        int row = m0 + mbase + am * 16 + r;
#pragma unroll
        for (int an = 0; an < 4; an++) {
            int col = n0 + nbase + an * 8 + 2 * c;
            if (row < M)
                *(float2*)&C[(size_t)row * N + col] = make_float2(acc[am][an][0], acc[am][an][1]);
            if (row + 8 < M)
                *(float2*)&C[(size_t)(row + 8) * N + col] = make_float2(acc[am][an][2], acc[am][an][3]);
        }
    }
}

// ---------------- precompute Wa = W @ att per layer/head ----------------
// g_wsrc[(l*4+h)*128+k] = sum_c gat_w[l][k][h*128+c] * att_src[l][h][c]
__global__ void k_watt(const float* __restrict__ gw,
                       const float* __restrict__ as_, const float* __restrict__ ad_) {
    int l = blockIdx.x, h = blockIdx.y;
    int k = threadIdx.x;
    __shared__ float s_as[128], s_ad[128];
    s_as[k] = as_[(l * 4 + h) * 128 + k];
    s_ad[k] = ad_[(l * 4 + h) * 128 + k];
    __syncthreads();
    const float* wrow = gw + ((size_t)l * 128 + k) * 512 + h * 128;
    float ss = 0.0f, sd = 0.0f;
#pragma unroll 8
    for (int cc = 0; cc < 128; cc++) {
        float w = wrow[cc];
        ss += w * s_as[cc];
        sd += w * s_ad[cc];
    }
    g_wsrc[(l * 4 + h) * 128 + k] = ss;
    g_wdst[(l * 4 + h) * 128 + k] = sd;
}

// ---------------- logits from h directly: als = h @ Wa ----------------
__global__ void k_logits2(const float* __restrict__ h, int l) {
    int node = blockIdx.x * 4 + (threadIdx.x >> 5);
    int lane = threadIdx.x & 31;
    if (node >= NN) return;
    float4 hv = *(const float4*)&h[(size_t)node * HD + lane * 4];
#pragma unroll
    for (int hh = 0; hh < 4; hh++) {
        float4 ws = *(const float4*)&g_wsrc[(l * 4 + hh) * 128 + lane * 4];
        float4 wd = *(const float4*)&g_wdst[(l * 4 + hh) * 128 + lane * 4];
        float ds = hv.x * ws.x + hv.y * ws.y + hv.z * ws.z + hv.w * ws.w;
        float dd = hv.x * wd.x + hv.y * wd.y + hv.z * wd.z + hv.w * wd.w;
#pragma unroll
        for (int off = 16; off > 0; off >>= 1) {
            ds += __shfl_down_sync(0xffffffffu, ds, off);
            dd += __shfl_down_sync(0xffffffffu, dd, off);
        }
        if (lane == 0) { g_als[node * 4 + hh] = ds; g_ald[node * 4 + hh] = dd; }
    }
}

// ------- fused GAT gather: softmax + weighted sum + head-mean + bias + BN (+relu) -------
__global__ void k_gather(const float* __restrict__ xh,
                         const float* __restrict__ bias,
                         const float* __restrict__ bng, const float* __restrict__ bnb,
                         const float* __restrict__ bnm, const float* __restrict__ bnv,
                         int do_relu, float* __restrict__ hout) {
    int node = blockIdx.x * 4 + (threadIdx.x >> 5);
    int lane = threadIdx.x & 31;
    if (node >= NN) return;
    int beg = g_rowptr[node], end = g_rowptr[node + 1];
    int h = lane & 3;
    float myald = g_ald[node * 4 + h];

    float mx = -1e30f;
    for (int i = beg; i < end; i++) {
        int s = g_csrsrc[i];
        float a = g_als[s * 4 + h] + myald;
        a = (a >= 0.0f) ? a : 0.2f * a;
        mx = fmaxf(mx, a);
    }

    float4 acc0 = make_float4(0, 0, 0, 0), acc1 = acc0, acc2 = acc0, acc3 = acc0;
    float sum = 0.0f;
    for (int i = beg; i < end; i++) {
        int s = g_csrsrc[i];
        float a = g_als[s * 4 + h] + myald;
        a = (a >= 0.0f) ? a : 0.2f * a;
        float w = expf(a - mx);
        sum += w;
        float w0 = __shfl_sync(0xffffffffu, w, 0);
        float w1 = __shfl_sync(0xffffffffu, w, 1);
        float w2 = __shfl_sync(0xffffffffu, w, 2);
        float w3 = __shfl_sync(0xffffffffu, w, 3);
        const float4* xp = (const float4*)(xh + (size_t)s * 512);
        float4 v0 = xp[lane];
        float4 v1 = xp[32 + lane];
        float4 v2 = xp[64 + lane];
        float4 v3 = xp[96 + lane];
        acc0.x += w0 * v0.x; acc0.y += w0 * v0.y; acc0.z += w0 * v0.z; acc0.w += w0 * v0.w;
        acc1.x += w1 * v1.x; acc1.y += w1 * v1.y; acc1.z += w1 * v1.z; acc1.w += w1 * v1.w;
        acc2.x += w2 * v2.x; acc2.y += w2 * v2.y; acc2.z += w2 * v2.z; acc2.w += w2 * v2.w;
        acc3.x += w3 * v3.x; acc3.y += w3 * v3.y; acc3.z += w3 * v3.z; acc3.w += w3 * v3.w;
    }
    float s0 = __shfl_sync(0xffffffffu, sum, 0);
    float s1 = __shfl_sync(0xffffffffu, sum, 1);
    float s2 = __shfl_sync(0xffffffffu, sum, 2);
    float s3 = __shfl_sync(0xffffffffu, sum, 3);
    float i0 = 1.0f / (s0 + 1e-16f), i1 = 1.0f / (s1 + 1e-16f);
    float i2 = 1.0f / (s2 + 1e-16f), i3 = 1.0f / (s3 + 1e-16f);

    int c = lane * 4;
    float4 bia = *(const float4*)&bias[c];
    float4 g4  = *(const float4*)&bng[c];
    float4 b4  = *(const float4*)&bnb[c];
    float4 m4  = *(const float4*)&bnm[c];
    float4 v4  = *(const float4*)&bnv[c];
    float4 o;
    o.x = 0.25f * (acc0.x * i0 + acc1.x * i1 + acc2.x * i2 + acc3.x * i3) + bia.x;
    o.y = 0.25f * (acc0.y * i0 + acc1.y * i1 + acc2.y * i2 + acc3.y * i3) + bia.y;
    o.z = 0.25f * (acc0.z * i0 + acc1.z * i1 + acc2.z * i2 + acc3.z * i3) + bia.z;
    o.w = 0.25f * (acc0.w * i0 + acc1.w * i1 + acc2.w * i2 + acc3.w * i3) + bia.w;
    o.x = (o.x - m4.x) * rsqrtf(v4.x + 1e-5f) * g4.x + b4.x;
    o.y = (o.y - m4.y) * rsqrtf(v4.y + 1e-5f) * g4.y + b4.y;
    o.z = (o.z - m4.z) * rsqrtf(v4.z + 1e-5f) * g4.z + b4.z;
    o.w = (o.w - m4.w) * rsqrtf(v4.w + 1e-5f) * g4.w + b4.w;
    if (do_relu) {
        o.x = fmaxf(o.x, 0.f); o.y = fmaxf(o.y, 0.f);
        o.z = fmaxf(o.z, 0.f); o.w = fmaxf(o.w, 0.f);
    }
    *(float4*)&hout[(size_t)node * HD + c] = o;
}

// ------- fused edge MLP v2: 16 edges/block, register-tiled z1@W2 ---------------
__global__ __launch_bounds__(256) void k_edge_mlp2(
        const int* __restrict__ src, const int* __restrict__ dst,
        const float* __restrict__ eattr,
        const float* __restrict__ em1b, const float* __restrict__ wc,
        const float* __restrict__ lng, const float* __restrict__ lnb,
        const float* __restrict__ w2, const float* __restrict__ b2,
        const float* __restrict__ w3, const float* __restrict__ b3,
        float* __restrict__ out) {
    __shared__ float sz1[16][128];
    __shared__ float spart[4][16][64];
    __shared__ float sea[2][8];
    __shared__ float red1[2][4], red2[2][4];

    int tid = threadIdx.x;
    int e_base = blockIdx.x * 16;
    int t = tid & 127, half = tid >> 7;

    for (int g = 0; g < 8; g++) {
        int el = g * 2 + half;
        int e = e_base + el;
        int s = src[e], d = dst[e];
        if (t < 8) sea[half][t] = eattr[e * 8 + t];
        __syncthreads();
        float v = g_p[s * HD + t] + g_q[d * HD + t] + em1b[t];
#pragma unroll
        for (int j = 0; j < 8; j++) v += sea[half][j] * wc[j * HD + t];
        float su = v, sq = v * v;
#pragma unroll
        for (int off = 16; off > 0; off >>= 1) {
            su += __shfl_down_sync(0xffffffffu, su, off);
            sq += __shfl_down_sync(0xffffffffu, sq, off);
        }
        if ((t & 31) == 0) { red1[half][t >> 5] = su; red2[half][t >> 5] = sq; }
        __syncthreads();
        float mu  = (red1[half][0] + red1[half][1] + red1[half][2] + red1[half][3]) * (1.0f / HD);
        float var = (red2[half][0] + red2[half][1] + red2[half][2] + red2[half][3]) * (1.0f / HD) - mu * mu;
        float y = (v - mu) * rsqrtf(var + 1e-5f) * lng[t] + lnb[t];
        sz1[el][t] = fmaxf(y, 0.0f);
    }
    __syncthreads();

    {
        int o4 = (tid & 15) * 4;
        int eg = (tid >> 4) & 3;
        int ks = tid >> 6;
        float4 a0 = make_float4(0, 0, 0, 0), a1 = a0, a2 = a0, a3 = a0;
        int kbeg = ks * 32;
#pragma unroll 8
        for (int k = kbeg; k < kbeg + 32; k++) {
            float4 w4 = *(const float4*)&w2[k * 64 + o4];
            float z0 = sz1[eg * 4 + 0][k];
            float z1v = sz1[eg * 4 + 1][k];
            float z2v = sz1[eg * 4 + 2][k];
            float z3v = sz1[eg * 4 + 3][k];
            a0.x += z0 * w4.x;  a0.y += z0 * w4.y;  a0.z += z0 * w4.z;  a0.w += z0 * w4.w;
            a1.x += z1v * w4.x; a1.y += z1v * w4.y; a1.z += z1v * w4.z; a1.w += z1v * w4.w;
            a2.x += z2v * w4.x; a2.y += z2v * w4.y; a2.z += z2v * w4.z; a2.w += z2v * w4.w;
            a3.x += z3v * w4.x; a3.y += z3v * w4.y; a3.z += z3v * w4.z; a3.w += z3v * w4.w;
        }
        *(float4*)&spart[ks][eg * 4 + 0][o4] = a0;
        *(float4*)&spart[ks][eg * 4 + 1][o4] = a1;
        *(float4*)&spart[ks][eg * 4 + 2][o4] = a2;
        *(float4*)&spart[ks][eg * 4 + 3][o4] = a3;
    }
    __syncthreads();

    {
        int e2 = tid >> 4;
        int ob = (tid & 15) * 4;
        float val = 0.0f;
#pragma unroll
        for (int i = 0; i < 4; i++) {
            int o = ob + i;
            float ssum = spart[0][e2][o] + spart[1][e2][o] + spart[2][e2][o] + spart[3][e2][o];
            float z2 = fmaxf(ssum + b2[o], 0.0f);
            val += z2 * w3[o];
        }
#pragma unroll
        for (int off = 8; off > 0; off >>= 1)
            val += __shfl_down_sync(0xffffffffu, val, off, 16);
        if ((tid & 15) == 0) out[e_base + e2] = val + b3[0];
    }
}

// ---------------- launch ----------------
extern "C" void kernel_launch(void* const* d_in, const int* in_sizes, int n_in,
                              void* d_out, int out_size) {
    const float* x       = (const float*)d_in[0];
    const int*   ei      = (const int*)d_in[1];
    const float* eattr   = (const float*)d_in[2];
    const int*   shock   = (const int*)d_in[3];
    const float* enc_w   = (const float*)d_in[4];
    const float* enc_b   = (const float*)d_in[5];
    const float* enc_lng = (const float*)d_in[6];
    const float* enc_lnb = (const float*)d_in[7];
    const float* gat_w   = (const float*)d_in[8];
    const float* att_src = (const float*)d_in[9];
    const float* att_dst = (const float*)d_in[10];
    const float* gat_bias= (const float*)d_in[11];
    const float* bn_g    = (const float*)d_in[12];
    const float* bn_b    = (const float*)d_in[13];
    const float* bn_m    = (const float*)d_in[14];
    const float* bn_v    = (const float*)d_in[15];
    const float* em1_w   = (const float*)d_in[16];
    const float* em1_b   = (const float*)d_in[17];
    const float* em_lng  = (const float*)d_in[18];
    const float* em_lnb  = (const float*)d_in[19];
    const float* em2_w   = (const float*)d_in[20];
    const float* em2_b   = (const float*)d_in[21];
    const float* em3_w   = (const float*)d_in[22];
    const float* em3_b   = (const float*)d_in[23];
    const int* src = ei;
    const int* dst = ei + EE;
    float* out = (float*)d_out;

    float *ph, *ph2, *pxh, *pp, *pq;
    cudaGetSymbolAddress((void**)&ph,  g_h);
    cudaGetSymbolAddress((void**)&ph2, g_h2);
    cudaGetSymbolAddress((void**)&pxh, g_xh);
    cudaGetSymbolAddress((void**)&pp,  g_p);
    cudaGetSymbolAddress((void**)&pq,  g_q);

    // graph prep: downstream flags + CSR by destination (with self-loops)
    k_zero_misc<<<(NN + 255) / 256, 256>>>();
    k_down<<<(EE + 255) / 256, 256>>>(src, dst, shock);
    k_count<<<(E2 + 255) / 256, 256>>>(dst);
    int nb = (NN + 1023) / 1024;
    k_scan1<<<nb, 1024>>>();
    k_scan2<<<1, 32>>>(nb);
    k_scan3<<<(NN + 255) / 256, 256>>>();
    k_scatter<<<(E2 + 255) / 256, 256>>>(src, dst);

    // attention weight pre-reduction: Wa = W @ att  (all layers/heads)
    k_watt<<<dim3(3, 4), 128>>>(gat_w, att_src, att_dst);

    // node encoder
    k_encoder<<<NN, 128>>>(x, shock, enc_w, enc_b, enc_lng, enc_lnb, ph);

    // 3 GAT layers
    float* hin = ph;
    float* hout = ph2;
    int gx = (NN + 127) / 128;
    for (int l = 0; l < 3; l++) {
        k_logits2<<<(NN + 3) / 4, 128>>>(hin, l);
        gemm_tf32<<<dim3(gx, 4), 256>>>(hin, gat_w + (size_t)l * HD * 512, pxh, NN, 512, HD);
        k_gather<<<(NN + 3) / 4, 128>>>(pxh, gat_bias + l * HD,
                                        bn_g + l * HD, bn_b + l * HD, bn_m + l * HD, bn_v + l * HD,
                                        (l < 2) ? 1 : 0, hout);
        float* tmp = hin; hin = hout; hout = tmp;
    }
    // hin now holds the final node embeddings

    // edge MLP first layer factored: p = h @ W_a, q = h @ W_b
    gemm_tf32<<<dim3(gx, 1), 256>>>(hin, em1_w,            pp, NN, HD, HD);
    gemm_tf32<<<dim3(gx, 1), 256>>>(hin, em1_w + 128 * HD, pq, NN, HD, HD);

    // fused edge predictor (EE = 12500 * 16 exactly)
    k_edge_mlp2<<<EE / 16, 256>>>(src, dst, eattr, em1_b, em1_w + 256 * HD,
                                  em_lng, em_lnb, em2_w, em2_b, em3_w, em3_b, out);
}